// round 1
// baseline (speedup 1.0000x reference)
#include <cuda_runtime.h>
#include <cstdint>

// ---------------- constants ----------------
#define MEANC 0.1307f
#define STDC  0.3081f
#define NIN   784
#define NH    2048
#define NOUT  10

// ---------------- scratch (device globals; no allocation allowed) ----------------
__device__ float g_bufh[2][NH * NH];
__device__ float g_bufl[2][NH * NH];
__device__ float g_xa[NH];
__device__ float g_xb[NH];
__device__ float g_low[NH];
__device__ float g_high[NH];
__device__ float g_wl[4 * NH];
__device__ float g_wh[4 * NH];
__device__ float g_bhr[4 * NH];
__device__ float g_bh[NH];
__device__ float g_bl[NH];
__device__ float g_x0[NIN];
__device__ float g_l0[NIN];
__device__ float g_h0[NIN];

// ---------------- helpers ----------------
__device__ __forceinline__ void blkred2(float& a, float& b) {
    const unsigned full = 0xffffffffu;
    #pragma unroll
    for (int o = 16; o > 0; o >>= 1) {
        a += __shfl_down_sync(full, a, o);
        b += __shfl_down_sync(full, b, o);
    }
    __shared__ float sa[8], sb[8];
    int w = threadIdx.x >> 5, lane = threadIdx.x & 31;
    if (lane == 0) { sa[w] = a; sb[w] = b; }
    __syncthreads();
    if (w == 0) {
        a = (lane < 8) ? sa[lane] : 0.f;
        b = (lane < 8) ? sb[lane] : 0.f;
        #pragma unroll
        for (int o = 4; o > 0; o >>= 1) {
            a += __shfl_down_sync(full, a, o);
            b += __shfl_down_sync(full, b, o);
        }
    }
}

// ---------------- kernels ----------------
__global__ void normalize_k(const float* __restrict__ x, const float* __restrict__ lo,
                            const float* __restrict__ hi,
                            float* __restrict__ x0, float* __restrict__ l0,
                            float* __restrict__ h0, int n) {
    int i = blockIdx.x * blockDim.x + threadIdx.x;
    if (i < n) {
        x0[i] = (x[i] - MEANC) / STDC;
        l0[i] = (lo[i] - MEANC) / STDC;
        h0[i] = (hi[i] - MEANC) / STDC;
    }
}

// x_out = W @ x_in + b ; one warp per row
__global__ void matvec_k(const float* __restrict__ W, const float* __restrict__ xin,
                         const float* __restrict__ b, float* __restrict__ xout,
                         int M, int K) {
    int row = blockIdx.x * (blockDim.x >> 5) + (threadIdx.x >> 5);
    if (row >= M) return;
    int lane = threadIdx.x & 31;
    float s = 0.f;
    const float* wr = W + (size_t)row * K;
    for (int k = lane; k < K; k += 32) s += wr[k] * xin[k];
    #pragma unroll
    for (int o = 16; o > 0; o >>= 1) s += __shfl_down_sync(0xffffffffu, s, o);
    if (lane == 0) xout[row] = s + b[row];
}

// Fused relu-backsub transform + relu bias + following-linear bias.
//   oh = (mh>0 ? mh*wh : mh*wl)*mask ; ol = (ml>0 ? ml*wl : ml*wh)*mask ; mask=(wh!=0)
//   bh[m] (+)= sum_k max(mh,0)*mask*bhr[k] + oh*bj[k]
//   bl[m] (+)= sum_k min(ml,0)*mask*bhr[k] + ol*bj[k]
// binit != nullptr -> initialize bh/bl = binit[m] + partial (first step of a chain)
// Safe with src == dst (pure elementwise on the matrices).
__global__ void relu_linear_backsub_k(const float* __restrict__ srch, const float* __restrict__ srcl,
                                      float* __restrict__ dsth, float* __restrict__ dstl,
                                      const float* __restrict__ wld, const float* __restrict__ whd,
                                      const float* __restrict__ bhrd, const float* __restrict__ bj,
                                      float* __restrict__ bh, float* __restrict__ bl,
                                      const float* __restrict__ binit, int K) {
    int m = blockIdx.x;
    size_t base = (size_t)m * K;
    float sh = 0.f, sl = 0.f;
    for (int k = threadIdx.x; k < K; k += blockDim.x) {
        float whk = whd[k], wlk = wld[k], brk = bhrd[k], bjk = bj[k];
        float mask = (whk != 0.f) ? 1.f : 0.f;
        float mh = srch[base + k], ml = srcl[base + k];
        float oh = (mh > 0.f ? mh * whk : mh * wlk) * mask;
        float ol = (ml > 0.f ? ml * wlk : ml * whk) * mask;
        dsth[base + k] = oh;
        dstl[base + k] = ol;
        sh += fmaxf(mh, 0.f) * mask * brk + oh * bjk;
        sl += fminf(ml, 0.f) * mask * brk + ol * bjk;
    }
    blkred2(sh, sl);
    if (threadIdx.x == 0) {
        if (binit) { bh[m] = binit[m] + sh; bl[m] = binit[m] + sl; }
        else       { bh[m] += sh;           bl[m] += sl; }
    }
}

// Final interval evaluation against the input box.
__global__ void box_k(const float* __restrict__ Ah, const float* __restrict__ Al,
                      const float* __restrict__ bh, const float* __restrict__ bl,
                      const float* __restrict__ l0, const float* __restrict__ h0,
                      float* __restrict__ lowv, float* __restrict__ highv, int K) {
    int m = blockIdx.x;
    size_t base = (size_t)m * K;
    float sh = 0.f, sl = 0.f;
    for (int k = threadIdx.x; k < K; k += blockDim.x) {
        float l0k = l0[k], h0k = h0[k];
        float ah = Ah[base + k];
        sh += (ah >= 0.f) ? ah * h0k : ah * l0k;
        float al = Al[base + k];
        sl += (al >= 0.f) ? al * l0k : al * h0k;
    }
    blkred2(sh, sl);
    if (threadIdx.x == 0) {
        highv[m] = bh[m] + sh;
        lowv[m]  = bl[m] + sl;
    }
}

// DeepPoly relu relaxation -> per-neuron diagonals; x <- max(x,0) in place.
__global__ void relu_abs_k(float* __restrict__ x, const float* __restrict__ lowv,
                           const float* __restrict__ highv,
                           float* __restrict__ wl, float* __restrict__ wh,
                           float* __restrict__ bhr, int n) {
    int i = blockIdx.x * blockDim.x + threadIdx.x;
    if (i >= n) return;
    float l = lowv[i], h = highv[i];
    bool crossing = (l < 0.f) && (h > 0.f);
    float denom = crossing ? (h - l) : 1.f;
    float ubs = crossing ? h / denom : 0.f;
    float ubi = crossing ? -(l * h) / denom : 0.f;
    float lam = (l * l > h * h) ? 0.f : 1.f;
    float keep = (h <= 0.f) ? 0.f : 1.f;
    wh[i]  = crossing ? ubs : keep;
    wl[i]  = crossing ? lam : keep;
    bhr[i] = ubi;
    x[i] = fmaxf(x[i], 0.f);
}

__global__ void write_out_k(const float* __restrict__ x5, const float* __restrict__ lowv,
                            const float* __restrict__ highv, float* __restrict__ out) {
    int i = threadIdx.x;
    if (i < NOUT) {
        out[i]          = x5[i];
        out[NOUT + i]   = lowv[i];
        out[2*NOUT + i] = highv[i];
    }
}

// ---------------- SGEMM: C = A(MxK) @ B(KxN), all row-major, K % 8 == 0, N % 4 == 0
__global__ void __launch_bounds__(256) sgemm_k(int M, int N, int K,
                                               const float* __restrict__ A,
                                               const float* __restrict__ B,
                                               float* __restrict__ C) {
    __shared__ float As[8][128];
    __shared__ float Bs[8][128];
    const int tid = threadIdx.x;
    const int tx = tid & 15;
    const int ty = tid >> 4;
    const int row0 = blockIdx.y * 128;
    const int col0 = blockIdx.x * 128;

    const int a_row = tid >> 1;
    const int a_col = (tid & 1) << 2;
    const int b_row = tid >> 5;
    const int b_colo = (tid & 31) << 2;

    const int gArow = row0 + a_row;
    const bool aValid = gArow < M;
    const int gBcol = col0 + b_colo;
    const bool bValid = gBcol < N;

    float acc[8][8];
    #pragma unroll
    for (int i = 0; i < 8; ++i)
        #pragma unroll
        for (int j = 0; j < 8; ++j) acc[i][j] = 0.f;

    for (int k0 = 0; k0 < K; k0 += 8) {
        float4 av = aValid ? *reinterpret_cast<const float4*>(A + (size_t)gArow * K + k0 + a_col)
                           : make_float4(0.f, 0.f, 0.f, 0.f);
        As[a_col + 0][a_row] = av.x;
        As[a_col + 1][a_row] = av.y;
        As[a_col + 2][a_row] = av.z;
        As[a_col + 3][a_row] = av.w;
        float4 bv = bValid ? *reinterpret_cast<const float4*>(B + (size_t)(k0 + b_row) * N + gBcol)
                           : make_float4(0.f, 0.f, 0.f, 0.f);
        *reinterpret_cast<float4*>(&Bs[b_row][b_colo]) = bv;
        __syncthreads();
        #pragma unroll
        for (int kk = 0; kk < 8; ++kk) {
            float4 a0 = *reinterpret_cast<const float4*>(&As[kk][ty * 8]);
            float4 a1 = *reinterpret_cast<const float4*>(&As[kk][ty * 8 + 4]);
            float4 b0 = *reinterpret_cast<const float4*>(&Bs[kk][tx * 8]);
            float4 b1 = *reinterpret_cast<const float4*>(&Bs[kk][tx * 8 + 4]);
            float ar[8] = {a0.x, a0.y, a0.z, a0.w, a1.x, a1.y, a1.z, a1.w};
            float br[8] = {b0.x, b0.y, b0.z, b0.w, b1.x, b1.y, b1.z, b1.w};
            #pragma unroll
            for (int i = 0; i < 8; ++i)
                #pragma unroll
                for (int j = 0; j < 8; ++j)
                    acc[i][j] += ar[i] * br[j];
        }
        __syncthreads();
    }

    #pragma unroll
    for (int i = 0; i < 8; ++i) {
        int r = row0 + ty * 8 + i;
        if (r >= M) continue;
        #pragma unroll
        for (int j = 0; j < 8; j += 4) {
            int c = col0 + tx * 8 + j;
            if (c < N) {
                float4 v = make_float4(acc[i][j], acc[i][j + 1], acc[i][j + 2], acc[i][j + 3]);
                *reinterpret_cast<float4*>(C + (size_t)r * N + c) = v;
            }
        }
    }
}

// ---------------- driver ----------------
extern "C" void kernel_launch(void* const* d_in, const int* in_sizes, int n_in,
                              void* d_out, int out_size) {
    const float* x  = (const float*)d_in[0];
    const float* lo = (const float*)d_in[1];
    const float* hi = (const float*)d_in[2];
    const float* W[5];
    const float* b[5];
    for (int i = 0; i < 5; ++i) {
        W[i] = (const float*)d_in[3 + 2 * i];
        b[i] = (const float*)d_in[4 + 2 * i];
    }
    float* out = (float*)d_out;

    void* p;
    float *bufh[2], *bufl[2];
    cudaGetSymbolAddress(&p, g_bufh); bufh[0] = (float*)p; bufh[1] = bufh[0] + (size_t)NH * NH;
    cudaGetSymbolAddress(&p, g_bufl); bufl[0] = (float*)p; bufl[1] = bufl[0] + (size_t)NH * NH;
    float *xa, *xb, *lowv, *highv, *wl, *wh, *bhr, *bh, *bl, *x0, *l0, *h0;
    cudaGetSymbolAddress(&p, g_xa);   xa = (float*)p;
    cudaGetSymbolAddress(&p, g_xb);   xb = (float*)p;
    cudaGetSymbolAddress(&p, g_low);  lowv = (float*)p;
    cudaGetSymbolAddress(&p, g_high); highv = (float*)p;
    cudaGetSymbolAddress(&p, g_wl);   wl = (float*)p;
    cudaGetSymbolAddress(&p, g_wh);   wh = (float*)p;
    cudaGetSymbolAddress(&p, g_bhr);  bhr = (float*)p;
    cudaGetSymbolAddress(&p, g_bh);   bh = (float*)p;
    cudaGetSymbolAddress(&p, g_bl);   bl = (float*)p;
    cudaGetSymbolAddress(&p, g_x0);   x0 = (float*)p;
    cudaGetSymbolAddress(&p, g_l0);   l0 = (float*)p;
    cudaGetSymbolAddress(&p, g_h0);   h0 = (float*)p;

    normalize_k<<<(NIN + 255) / 256, 256>>>(x, lo, hi, x0, l0, h0, NIN);

    // ---- layer 1 (index 0): backsub chain is just W1 itself ----
    matvec_k<<<NH / 8, 256>>>(W[0], x0, b[0], xa, NH, NIN);
    box_k<<<NH, 256>>>(W[0], W[0], b[0], b[0], l0, h0, lowv, highv, NIN);
    relu_abs_k<<<NH / 256, 256>>>(xa, lowv, highv, wl + 0 * NH, wh + 0 * NH, bhr + 0 * NH, NH);

    float* xin = xa;
    float* xout = xb;
    for (int i = 1; i < 5; ++i) {
        int M = (i == 4) ? NOUT : NH;
        matvec_k<<<(M + 7) / 8, 256>>>(W[i], xin, b[i], xout, M, NH);

        const float* srch = W[i];
        const float* srcl = W[i];
        int cur = 0;
        bool first = true;
        for (int j = i - 1; j >= 0; --j) {
            float* th = bufh[cur];
            float* tl = bufl[cur];
            relu_linear_backsub_k<<<M, 256>>>(srch, srcl, th, tl,
                                              wl + j * NH, wh + j * NH, bhr + j * NH, b[j],
                                              bh, bl, first ? b[i] : nullptr, NH);
            int Ng = (j == 0) ? NIN : NH;
            dim3 grid((Ng + 127) / 128, (M + 127) / 128);
            float* oh = bufh[cur ^ 1];
            float* ol = bufl[cur ^ 1];
            sgemm_k<<<grid, 256>>>(M, Ng, NH, th, W[j], oh);
            sgemm_k<<<grid, 256>>>(M, Ng, NH, tl, W[j], ol);
            srch = oh;
            srcl = ol;
            cur ^= 1;
            first = false;
        }
        box_k<<<M, 256>>>(srch, srcl, bh, bl, l0, h0, lowv, highv, NIN);
        if (i < 4) {
            relu_abs_k<<<NH / 256, 256>>>(xout, lowv, highv,
                                          wl + i * NH, wh + i * NH, bhr + i * NH, NH);
            float* t = xin; xin = xout; xout = t;
        } else {
            write_out_k<<<1, 32>>>(xout, lowv, highv, out);
        }
    }
    (void)in_sizes; (void)n_in; (void)out_size;
}